// round 2
// baseline (speedup 1.0000x reference)
#include <cuda_runtime.h>
#include <cuda_bf16.h>
#include <math.h>

// Problem constants
// B=8, C=64, H=64, W=64, R=16, HD=4, D=16, K=4, OC=1024
// NPX = 32768 pixels.  x layout [B,C,H,W]: idx = ((b*64+c)*64+h)*64+w
// channel stride = 4096, image stride = 262144.

#define NPX 32768

__device__ float    g_qk[1024];   // q value per output channel o = r*64 + hd*16 + d
__device__ float    g_cn[64];     // null-branch constant per (r,hd)
__device__ unsigned g_sel[NPX];   // packed top-4 rim ids (4 x 8 bits) per pixel

// ---------- packed f32x2 helpers ----------
__device__ __forceinline__ unsigned long long pk2(float lo, float hi) {
    unsigned long long r;
    asm("mov.b64 %0, {%1, %2};" : "=l"(r) : "f"(lo), "f"(hi));
    return r;
}
__device__ __forceinline__ void fma2(unsigned long long& d, unsigned long long a,
                                     unsigned long long b) {
    asm("fma.rn.f32x2 %0, %1, %2, %0;" : "+l"(d) : "l"(a), "l"(b));
}
__device__ __forceinline__ void unpk(unsigned long long v, float& lo, float& hi) {
    asm("mov.b64 {%0, %1}, %2;" : "=f"(lo), "=f"(hi) : "l"(v));
}

// ============================================================
// Kernel A: tiny precompute of q (per channel) and null constants.
// One block, 64 threads; thread t = (r,hd) pair.
// ============================================================
__global__ void kA(const float* __restrict__ rims, const float* __restrict__ Wq,
                   const float* __restrict__ bq, const float* __restrict__ bk) {
    int t = threadIdx.x;          // 0..63 = r*4+hd
    int r = t >> 2;
    const float* rrow = rims + r * 64;
    float cn = 0.f;
    for (int d = 0; d < 16; ++d) {
        int o = t * 16 + d;       // == r*64 + hd*16 + d
        const float* wrow = Wq + o * 64;
        float s = bq[o];
#pragma unroll 16
        for (int c = 0; c < 64; ++c) s = fmaf(rrow[c], wrow[c], s);
        float q = fmaxf(s, 0.f);
        g_qk[o] = q;
        cn += fmaxf(bk[o], 0.f) * q;
    }
    g_cn[t] = cn;
}

// ============================================================
// Kernel B: per-pixel scores + top-4 rim selection.
// Block = 64 pixels (one w-row), 256 threads.
// keyf GEMM [1024 out x 64 px, K=64] done in 8 chunks of 128 outputs,
// register tile 8 outputs x 4 pixels per thread, packed f32x2 FMAs.
// smem: xs[64][64] (16KB) + wks[64][132] (33KB, transposed+padded) + ip[64][64] (16KB)
// ============================================================
#define SMEM_B ((4096 + 64 * 132 + 4096) * 4)

__global__ void __launch_bounds__(256) kB(const float* __restrict__ x,
                                          const float* __restrict__ Wk,
                                          const float* __restrict__ bk) {
    extern __shared__ float sm[];
    float* xs  = sm;                 // [c][p] 64x64
    float* wks = sm + 4096;          // [k][o_l] 64x132 (pad 4 for LDS.128 align)
    float* ip  = wks + 64 * 132;     // [(r,hd)][p] 64x64

    const int tid  = threadIdx.x;
    const int pi0  = blockIdx.x * 64;
    const int bimg = pi0 >> 12;
    const int hw   = pi0 & 4095;
    const float* xbase = x + bimg * 262144 + hw;

    // load x tile (coalesced float4), layout xs[c][p]
    for (int e4 = tid; e4 < 1024; e4 += 256) {
        int c = e4 >> 4, p = (e4 & 15) << 2;
        *(float4*)(xs + c * 64 + p) = *(const float4*)(xbase + c * 4096 + p);
    }
    for (int e = tid; e < 4096; e += 256) ip[e] = 0.f;
    __syncthreads();

    const int tx = tid & 15;   // pixel group (4 px)
    const int ty = tid >> 4;   // output group (8 outs)

    for (int ch = 0; ch < 8; ++ch) {
        // stage Wk chunk transposed: wks[c][o_l] = Wk[ch*128+o_l][c]
        const float* wkc = Wk + ch * 128 * 64;
        for (int e4 = tid; e4 < 2048; e4 += 256) {
            int ol = e4 >> 4, c = (e4 & 15) << 2;
            float4 v = *(const float4*)(wkc + ol * 64 + c);
            wks[(c + 0) * 132 + ol] = v.x;
            wks[(c + 1) * 132 + ol] = v.y;
            wks[(c + 2) * 132 + ol] = v.z;
            wks[(c + 3) * 132 + ol] = v.w;
        }
        __syncthreads();

        unsigned long long acc[16];
#pragma unroll
        for (int i = 0; i < 16; ++i) acc[i] = 0ull;
        const int ob = ty * 8;

#pragma unroll 4
        for (int k = 0; k < 64; ++k) {
            ulonglong2 xv = *(const ulonglong2*)(xs + k * 64 + tx * 4);
            const float* wr = wks + k * 132 + ob;
            float4 w0 = *(const float4*)(wr);
            float4 w1 = *(const float4*)(wr + 4);
            unsigned long long wp;
            wp = pk2(w0.x, w0.x); fma2(acc[0],  xv.x, wp); fma2(acc[1],  xv.y, wp);
            wp = pk2(w0.y, w0.y); fma2(acc[2],  xv.x, wp); fma2(acc[3],  xv.y, wp);
            wp = pk2(w0.z, w0.z); fma2(acc[4],  xv.x, wp); fma2(acc[5],  xv.y, wp);
            wp = pk2(w0.w, w0.w); fma2(acc[6],  xv.x, wp); fma2(acc[7],  xv.y, wp);
            wp = pk2(w1.x, w1.x); fma2(acc[8],  xv.x, wp); fma2(acc[9],  xv.y, wp);
            wp = pk2(w1.y, w1.y); fma2(acc[10], xv.x, wp); fma2(acc[11], xv.y, wp);
            wp = pk2(w1.z, w1.z); fma2(acc[12], xv.x, wp); fma2(acc[13], xv.y, wp);
            wp = pk2(w1.w, w1.w); fma2(acc[14], xv.x, wp); fma2(acc[15], xv.y, wp);
        }

        // relu + *qk, reduce over this thread's 8 outputs (all in one d-group of 16)
        const int og = ch * 128 + ob;
        float p0 = 0.f, p1 = 0.f, p2 = 0.f, p3 = 0.f;
#pragma unroll
        for (int j = 0; j < 8; ++j) {
            float bkv = bk[og + j];
            float qkv = g_qk[og + j];
            float lo, hi;
            unpk(acc[2 * j], lo, hi);
            p0 += fmaxf(lo + bkv, 0.f) * qkv;
            p1 += fmaxf(hi + bkv, 0.f) * qkv;
            unpk(acc[2 * j + 1], lo, hi);
            p2 += fmaxf(lo + bkv, 0.f) * qkv;
            p3 += fmaxf(hi + bkv, 0.f) * qkv;
        }
        int g = ch * 8 + (ty >> 1);        // (r,hd) group index
        float* ipr = ip + g * 64 + tx * 4;
        atomicAdd(ipr + 0, p0);
        atomicAdd(ipr + 1, p1);
        atomicAdd(ipr + 2, p2);
        atomicAdd(ipr + 3, p3);
        __syncthreads();
    }

    // scores + top-4 (set only matters; ties -> lowest index, like lax.top_k)
    if (tid < 64) {
        int p = tid;
        float sc[16];
#pragma unroll
        for (int r = 0; r < 16; ++r) {
            float s = 0.f;
#pragma unroll
            for (int hd = 0; hd < 4; ++hd) {
                float v = ip[(r * 4 + hd) * 64 + p] - g_cn[r * 4 + hd];
                s += 1.f / (1.f + expf(-v));
            }
            sc[r] = s;
        }
        unsigned sel = 0;
#pragma unroll
        for (int kk = 0; kk < 4; ++kk) {
            int best = 0;
            float bvv = sc[0];
#pragma unroll
            for (int r = 1; r < 16; ++r)
                if (sc[r] > bvv) { bvv = sc[r]; best = r; }
            sel |= (unsigned)best << (8 * kk);
            sc[best] = -1e30f;
        }
        g_sel[pi0 + p] = sel;
    }
}

// ============================================================
// Kernel C: selective val + merge for top-4 rims, mean, relu, out projection.
// Block = 128 pixels, 256 threads.  Loop over 16 rims, staging Wv_r / Wm_r
// (32KB) in smem; a warp processes one (pixel,rim) task at a time.
// ============================================================
// smem float offsets
#define CO_XS   0                    // xs[64][128]            8192
#define CO_MACC 8192                 // macc[128][65]          8320
#define CO_WV   16512                // wv[64][65]  (c,o)      4160
#define CO_WM   20672                // wm[64][65]  (d,c)      4160
#define CO_WO   24832                // wo[64][65]  (cin,cout) 4160
#define CO_MISC 28992                // rimcnt(16 int) + rimlist(2048B=512f)
#define CO_VAL  (28992 + 16 + 512)   // valbuf[8][64]          512
#define SMEM_C  ((CO_VAL + 512) * 4)

__global__ void __launch_bounds__(256) kC(const float* __restrict__ x,
                                          const float* __restrict__ Wv,
                                          const float* __restrict__ bv,
                                          const float* __restrict__ Wm,
                                          const float* __restrict__ bm,
                                          const float* __restrict__ Wo,
                                          const float* __restrict__ bo,
                                          float* __restrict__ out) {
    extern __shared__ float sm[];
    float* xs   = sm + CO_XS;
    float* macc = sm + CO_MACC;
    float* wv   = sm + CO_WV;
    float* wm   = sm + CO_WM;
    float* wo   = sm + CO_WO;
    int* rimcnt = (int*)(sm + CO_MISC);
    unsigned char* rimlist = (unsigned char*)(rimcnt + 16);  // [16][128]
    float* valbuf = sm + CO_VAL;                             // [8][64]

    const int tid  = threadIdx.x;
    const int pi0  = blockIdx.x * 128;
    const int bimg = pi0 >> 12;
    const int hwb  = pi0 & 4095;
    const float* xbase = x + bimg * 262144 + hwb;

    // load x tile  xs[c][p]
    for (int e4 = tid; e4 < 2048; e4 += 256) {
        int c = e4 >> 5, p = (e4 & 31) << 2;
        *(float4*)(xs + c * 128 + p) = *(const float4*)(xbase + c * 4096 + p);
    }
    // zero merge accumulator
    for (int e = tid; e < 8192; e += 256) macc[(e >> 6) * 65 + (e & 63)] = 0.f;
    // Wo transposed: wo[cin][cout]
    for (int e4 = tid; e4 < 1024; e4 += 256) {
        int co = e4 >> 4, ci = (e4 & 15) << 2;
        float4 v = *(const float4*)(Wo + co * 64 + ci);
        wo[(ci + 0) * 65 + co] = v.x;
        wo[(ci + 1) * 65 + co] = v.y;
        wo[(ci + 2) * 65 + co] = v.z;
        wo[(ci + 3) * 65 + co] = v.w;
    }
    if (tid < 16) rimcnt[tid] = 0;
    __syncthreads();

    // build per-rim pixel lists
    if (tid < 128) {
        unsigned sel = g_sel[pi0 + tid];
#pragma unroll
        for (int j = 0; j < 4; ++j) {
            int r = (sel >> (8 * j)) & 15;
            int slot = atomicAdd(&rimcnt[r], 1);
            rimlist[r * 128 + slot] = (unsigned char)tid;
        }
    }
    __syncthreads();

    const int w = tid >> 5, lane = tid & 31;
    for (int r = 0; r < 16; ++r) {
        // stage Wv_r (transposed -> wv[c][o]) and Wm_r (transposed -> wm[d][c'])
        const float* Wvr = Wv + r * 4096;
        const float* Wmr = Wm + r * 4096;
        for (int e4 = tid; e4 < 1024; e4 += 256) {
            int o = e4 >> 4, c = (e4 & 15) << 2;
            float4 v = *(const float4*)(Wvr + o * 64 + c);
            wv[(c + 0) * 65 + o] = v.x;
            wv[(c + 1) * 65 + o] = v.y;
            wv[(c + 2) * 65 + o] = v.z;
            wv[(c + 3) * 65 + o] = v.w;
            float4 m = *(const float4*)(Wmr + o * 64 + c);  // row o = c' within rim, cols = d
            wm[(c + 0) * 65 + o] = m.x;
            wm[(c + 1) * 65 + o] = m.y;
            wm[(c + 2) * 65 + o] = m.z;
            wm[(c + 3) * 65 + o] = m.w;
        }
        __syncthreads();

        int n = rimcnt[r];
        float bv0 = bv[r * 64 + lane], bv1 = bv[r * 64 + lane + 32];
        float bm0 = bm[r * 64 + lane], bm1 = bm[r * 64 + lane + 32];
        for (int i = w; i < n; i += 8) {
            int p = rimlist[r * 128 + i];
            // val_r[64]: lane computes outputs lane, lane+32
            float a0 = bv0, a1 = bv1;
            const float* xp = xs + p;
#pragma unroll 8
            for (int c = 0; c < 64; ++c) {
                float xc = xp[c * 128];                // broadcast
                a0 = fmaf(xc, wv[c * 65 + lane], a0);
                a1 = fmaf(xc, wv[c * 65 + lane + 32], a1);
            }
            valbuf[w * 64 + lane]      = fmaxf(a0, 0.f);
            valbuf[w * 64 + lane + 32] = fmaxf(a1, 0.f);
            __syncwarp();
            // merged_r[c'] = sum_d val[d] * Wm[r,c',d]
            float m0 = bm0, m1 = bm1;
#pragma unroll 8
            for (int d = 0; d < 64; ++d) {
                float vd = valbuf[w * 64 + d];
                m0 = fmaf(vd, wm[d * 65 + lane], m0);
                m1 = fmaf(vd, wm[d * 65 + lane + 32], m1);
            }
            atomicAdd(macc + p * 65 + lane, m0);
            atomicAdd(macc + p * 65 + lane + 32, m1);
            __syncwarp();
        }
        __syncthreads();
    }

    // mid = relu(mean of 4)
    for (int e = tid; e < 8192; e += 256) {
        int idx = (e >> 6) * 65 + (e & 63);
        macc[idx] = fmaxf(macc[idx] * 0.25f, 0.f);
    }
    __syncthreads();

    // out projection: out[co] = relu(Wo @ mid + bo), coalesced writes over w
    {
        int p  = tid & 127;
        int cg = tid >> 7;  // 0..1
        float* outb = out + bimg * 262144 + hwb + p;
        const float* mr = macc + p * 65;
        for (int cb = 0; cb < 64; cb += 2) {
            int co = cb + cg;
            float acc = bo[co];
#pragma unroll 8
            for (int ci = 0; ci < 64; ++ci)
                acc = fmaf(mr[ci], wo[ci * 65 + co], acc);
            outb[co * 4096] = fmaxf(acc, 0.f);
        }
    }
}

// ============================================================
extern "C" void kernel_launch(void* const* d_in, const int* in_sizes, int n_in,
                              void* d_out, int out_size) {
    const float* x    = (const float*)d_in[0];
    const float* rims = (const float*)d_in[1];
    const float* Wk   = (const float*)d_in[2];
    const float* bk   = (const float*)d_in[3];
    const float* Wv   = (const float*)d_in[4];
    const float* bv   = (const float*)d_in[5];
    const float* Wq   = (const float*)d_in[6];
    const float* bq   = (const float*)d_in[7];
    const float* Wm   = (const float*)d_in[8];
    const float* bm   = (const float*)d_in[9];
    const float* Wo   = (const float*)d_in[10];
    const float* bo   = (const float*)d_in[11];
    float* out = (float*)d_out;

    cudaFuncSetAttribute(kB, cudaFuncAttributeMaxDynamicSharedMemorySize, SMEM_B);
    cudaFuncSetAttribute(kC, cudaFuncAttributeMaxDynamicSharedMemorySize, SMEM_C);

    kA<<<1, 64>>>(rims, Wq, bq, bk);
    kB<<<512, 256, SMEM_B>>>(x, Wk, bk);
    kC<<<256, 256, SMEM_C>>>(x, Wv, bv, Wm, bm, Wo, bo, out);
}

// round 3
// speedup vs baseline: 1.6487x; 1.6487x over previous
#include <cuda_runtime.h>
#include <cuda_bf16.h>
#include <math.h>

// B=8, C=64, H=64, W=64, R=16, HD=4, D=16, K=4, OC=1024
// NPX=32768; x[B,C,H,W]: ch stride 4096, img stride 262144.
#define NPX 32768

__device__ float    g_qk[1024];
__device__ float    g_cn[64];
__device__ unsigned g_sel[NPX];

__device__ __forceinline__ unsigned long long pk2(float lo, float hi) {
    unsigned long long r;
    asm("mov.b64 %0, {%1, %2};" : "=l"(r) : "f"(lo), "f"(hi));
    return r;
}
__device__ __forceinline__ void fma2(unsigned long long& d, unsigned long long a,
                                     unsigned long long b) {
    asm("fma.rn.f32x2 %0, %1, %2, %0;" : "+l"(d) : "l"(a), "l"(b));
}
__device__ __forceinline__ void unpk(unsigned long long v, float& lo, float& hi) {
    asm("mov.b64 {%0, %1}, %2;" : "=f"(lo), "=f"(hi) : "l"(v));
}

// ============================================================
// Kernel A: q precompute + null constants. 1 block x 1024 threads.
// ============================================================
__global__ void kA(const float* __restrict__ rims, const float* __restrict__ Wq,
                   const float* __restrict__ bq, const float* __restrict__ bk) {
    __shared__ float qs[1024];
    int o = threadIdx.x;
    int r = o >> 6;
    const float4* rrow = (const float4*)(rims + r * 64);
    const float4* wrow = (const float4*)(Wq + o * 64);
    float s = bq[o];
#pragma unroll
    for (int c4 = 0; c4 < 16; ++c4) {
        float4 w = wrow[c4];
        float4 rv = rrow[c4];
        s = fmaf(rv.x, w.x, s);
        s = fmaf(rv.y, w.y, s);
        s = fmaf(rv.z, w.z, s);
        s = fmaf(rv.w, w.w, s);
    }
    float q = fmaxf(s, 0.f);
    g_qk[o] = q;
    qs[o] = q * fmaxf(bk[o], 0.f);
    __syncthreads();
    if (o < 64) {
        float cn = 0.f;
#pragma unroll
        for (int d = 0; d < 16; ++d) cn += qs[o * 16 + d];
        g_cn[o] = cn;
    }
}

// ============================================================
// Kernel B: keyf GEMM + scores + top-4. Block = 64 px, 256 threads.
// Chunk = 256 outs; thread tile = 4 px x 16 outs (one full d-group).
// No atomics: in-register d-reduction, direct ip stores.
// smem: xs[64][64] + ws[256][68] + ip[64][64] = 102400 B
// ============================================================
#define KB_WS   4096
#define KB_IP   (4096 + 256 * 68)
#define SMEM_B  ((4096 + 256 * 68 + 4096) * 4)

__global__ void __launch_bounds__(256, 2) kB(const float* __restrict__ x,
                                             const float* __restrict__ Wk,
                                             const float* __restrict__ bk) {
    extern __shared__ float sm[];
    float* xs = sm;            // [c][p] 64x64
    float* ws = sm + KB_WS;    // [o_l][68]  (rows of Wk chunk, stride 68)
    float* ip = sm + KB_IP;    // [g][p] 64x64

    const int tid  = threadIdx.x;
    const int pi0  = blockIdx.x * 64;
    const int bimg = pi0 >> 12;
    const int hw   = pi0 & 4095;
    const float* xbase = x + bimg * 262144 + hw;

    for (int e4 = tid; e4 < 1024; e4 += 256) {
        int c = e4 >> 4, p = (e4 & 15) << 2;
        *(float4*)(xs + c * 64 + p) = *(const float4*)(xbase + c * 4096 + p);
    }

    const int tx = tid & 15;   // px group of 4
    const int ty = tid >> 4;   // out group of 16

    for (int ch = 0; ch < 4; ++ch) {
        __syncthreads();
        // stage 256 Wk rows (row-major, stride 68)
        const float4* wkc = (const float4*)(Wk + ch * 256 * 64);
        for (int e4 = tid; e4 < 4096; e4 += 256) {
            int o = e4 >> 4, c4 = (e4 & 15) << 2;
            *(float4*)(ws + o * 68 + c4) = wkc[e4];
        }
        __syncthreads();

        unsigned long long acc[32];
#pragma unroll
        for (int i = 0; i < 32; ++i) acc[i] = 0ull;
        const float* wrow = ws + (ty * 16) * 68;

#pragma unroll 2
        for (int k4 = 0; k4 < 16; ++k4) {
            unsigned long long xv[8];
#pragma unroll
            for (int i = 0; i < 4; ++i) {
                ulonglong2 v = *(const ulonglong2*)(xs + (k4 * 4 + i) * 64 + tx * 4);
                xv[2 * i] = v.x;
                xv[2 * i + 1] = v.y;
            }
#pragma unroll
            for (int j = 0; j < 16; ++j) {
                float4 w = *(const float4*)(wrow + j * 68 + k4 * 4);
                unsigned long long wp;
                wp = pk2(w.x, w.x); fma2(acc[2 * j], xv[0], wp); fma2(acc[2 * j + 1], xv[1], wp);
                wp = pk2(w.y, w.y); fma2(acc[2 * j], xv[2], wp); fma2(acc[2 * j + 1], xv[3], wp);
                wp = pk2(w.z, w.z); fma2(acc[2 * j], xv[4], wp); fma2(acc[2 * j + 1], xv[5], wp);
                wp = pk2(w.w, w.w); fma2(acc[2 * j], xv[6], wp); fma2(acc[2 * j + 1], xv[7], wp);
            }
        }

        // in-register d-group reduce: relu(acc+bk)*qk summed over the 16 outs
        const int og = ch * 256 + ty * 16;
        float p0 = 0.f, p1 = 0.f, p2 = 0.f, p3 = 0.f;
#pragma unroll
        for (int j = 0; j < 16; ++j) {
            float bkv = __ldg(bk + og + j);
            float qkv = g_qk[og + j];
            float lo, hi;
            unpk(acc[2 * j], lo, hi);
            p0 += fmaxf(lo + bkv, 0.f) * qkv;
            p1 += fmaxf(hi + bkv, 0.f) * qkv;
            unpk(acc[2 * j + 1], lo, hi);
            p2 += fmaxf(lo + bkv, 0.f) * qkv;
            p3 += fmaxf(hi + bkv, 0.f) * qkv;
        }
        int g = ch * 16 + ty;
        float* ipr = ip + g * 64 + tx * 4;
        ipr[0] = p0; ipr[1] = p1; ipr[2] = p2; ipr[3] = p3;
    }
    __syncthreads();

    if (tid < 64) {
        int p = tid;
        float sc[16];
#pragma unroll
        for (int r = 0; r < 16; ++r) {
            float s = 0.f;
#pragma unroll
            for (int hd = 0; hd < 4; ++hd) {
                float v = ip[(r * 4 + hd) * 64 + p] - g_cn[r * 4 + hd];
                s += 1.f / (1.f + expf(-v));
            }
            sc[r] = s;
        }
        unsigned sel = 0;
#pragma unroll
        for (int kk = 0; kk < 4; ++kk) {
            int best = 0;
            float bvv = sc[0];
#pragma unroll
            for (int r = 1; r < 16; ++r)
                if (sc[r] > bvv) { bvv = sc[r]; best = r; }
            sel |= (unsigned)best << (8 * kk);
            sc[best] = -1e30f;
        }
        g_sel[pi0 + p] = sel;
    }
}

// ============================================================
// Kernel C: selective val+merge (f32x2), mean, relu, out projection.
// Block = 128 px, 256 threads (8 warps). Warp task = (rim, 8 pixels).
// Lane = (out-group og 0..7 strided, pixel-pair 0..3). Weights via __ldg.
// smem: xs[64][128] (reused as wo[64][68]) + macc[64][132] + valbuf[8][64][8] + lists
// ============================================================
#define CC_XS     0
#define CC_MACC   8192
#define CC_VAL    (8192 + 64 * 132)
#define CC_MISC   (CC_VAL + 8 * 64 * 8)
// misc: rimcnt int[16]; rimlist u8[2048]; tasks int[96]; ntask int
#define SMEM_C    ((CC_MISC + 16 + 512 + 96 + 1) * 4)

__global__ void __launch_bounds__(256, 2) kC(const float* __restrict__ x,
                                             const float* __restrict__ Wv,
                                             const float* __restrict__ bv,
                                             const float* __restrict__ Wm,
                                             const float* __restrict__ bm,
                                             const float* __restrict__ Wo,
                                             const float* __restrict__ bo,
                                             float* __restrict__ out) {
    extern __shared__ float sm[];
    float* xs   = sm + CC_XS;     // [c][p] 64x128   (later reused as wo[64][68])
    float* macc = sm + CC_MACC;   // [c'][px] 64x132
    float* vbuf = sm + CC_VAL;    // [warp][d][slot] 8x64x8
    int* rimcnt = (int*)(sm + CC_MISC);
    unsigned char* rimlist = (unsigned char*)(rimcnt + 16);   // [16][128]
    int* tasks  = (int*)(rimlist + 2048);                      // [96]
    int* ntaskp = tasks + 96;

    const int tid  = threadIdx.x;
    const int w    = tid >> 5;
    const int lane = tid & 31;
    const int og   = lane >> 2;   // out group (strided: outs og + 8j)
    const int pp   = lane & 3;    // pixel-pair index (slots 2pp, 2pp+1)

    const int pi0  = blockIdx.x * 128;
    const int bimg = pi0 >> 12;
    const int hwb  = pi0 & 4095;
    const float* xbase = x + bimg * 262144 + hwb;

    for (int e4 = tid; e4 < 2048; e4 += 256) {
        int c = e4 >> 5, p = (e4 & 31) << 2;
        *(float4*)(xs + c * 128 + p) = *(const float4*)(xbase + c * 4096 + p);
    }
    for (int e = tid; e < 8448; e += 256) macc[e] = 0.f;
    if (tid < 16) rimcnt[tid] = 0;
    __syncthreads();

    if (tid < 128) {
        unsigned sel = g_sel[pi0 + tid];
#pragma unroll
        for (int j = 0; j < 4; ++j) {
            int r = (sel >> (8 * j)) & 15;
            int slot = atomicAdd(&rimcnt[r], 1);
            rimlist[r * 128 + slot] = (unsigned char)tid;
        }
    }
    __syncthreads();
    if (tid == 0) {
        int n = 0;
        for (int r = 0; r < 16; ++r) {
            int c = rimcnt[r];
            for (int s = 0; s < c; s += 8) tasks[n++] = (r << 8) | s;
        }
        *ntaskp = n;
    }
    __syncthreads();

    const int ntask = *ntaskp;
    const int nper  = (ntask + 7) >> 3;
    const int t0 = w * nper;
    const int t1 = min(t0 + nper, ntask);
    float* vb = vbuf + w * 512;

    for (int ti = t0; ti < t1; ++ti) {
        int tk = tasks[ti];
        int r = tk >> 8, s = tk & 255;
        int cnt = rimcnt[r] - s;
        if (cnt > 8) cnt = 8;
        const unsigned char* pl = rimlist + r * 128 + s;
        int i0 = pp * 2, i1 = i0 + 1;
        bool vA = i0 < cnt, vB = i1 < cnt;
        int pA = pl[vA ? i0 : 0];
        int pB = pl[vB ? i1 : 0];

        // ---- val: out d = og + 8j, sum over c ----
        unsigned long long acc[8];
#pragma unroll
        for (int j = 0; j < 8; ++j) acc[j] = 0ull;
        const float4* wvr = (const float4*)(Wv + r * 4096);
#pragma unroll 2
        for (int c4 = 0; c4 < 16; ++c4) {
            unsigned long long xv[4];
#pragma unroll
            for (int i = 0; i < 4; ++i) {
                const float* xr = xs + (c4 * 4 + i) * 128;
                xv[i] = pk2(xr[pA], xr[pB]);
            }
#pragma unroll
            for (int j = 0; j < 8; ++j) {
                float4 wq = __ldg(&wvr[(og + 8 * j) * 16 + c4]);
                fma2(acc[j], xv[0], pk2(wq.x, wq.x));
                fma2(acc[j], xv[1], pk2(wq.y, wq.y));
                fma2(acc[j], xv[2], pk2(wq.z, wq.z));
                fma2(acc[j], xv[3], pk2(wq.w, wq.w));
            }
        }
#pragma unroll
        for (int j = 0; j < 8; ++j) {
            int d = og + 8 * j;
            float bvv = __ldg(bv + r * 64 + d);
            float lo, hi;
            unpk(acc[j], lo, hi);
            float2 o2 = make_float2(fmaxf(lo + bvv, 0.f), fmaxf(hi + bvv, 0.f));
            *(float2*)(vb + d * 8 + pp * 2) = o2;
        }
        __syncwarp();

        // ---- merge: out c' = og + 8j, sum over d ----
        unsigned long long mcc[8];
#pragma unroll
        for (int j = 0; j < 8; ++j) mcc[j] = 0ull;
        const float4* wmr = (const float4*)(Wm + r * 4096);
#pragma unroll 2
        for (int d4 = 0; d4 < 16; ++d4) {
            unsigned long long vv[4];
#pragma unroll
            for (int i = 0; i < 4; ++i)
                vv[i] = *(const unsigned long long*)(vb + (d4 * 4 + i) * 8 + pp * 2);
#pragma unroll
            for (int j = 0; j < 8; ++j) {
                float4 wq = __ldg(&wmr[(og + 8 * j) * 16 + d4]);
                fma2(mcc[j], vv[0], pk2(wq.x, wq.x));
                fma2(mcc[j], vv[1], pk2(wq.y, wq.y));
                fma2(mcc[j], vv[2], pk2(wq.z, wq.z));
                fma2(mcc[j], vv[3], pk2(wq.w, wq.w));
            }
        }
#pragma unroll
        for (int j = 0; j < 8; ++j) {
            int cp = og + 8 * j;
            float bmv = __ldg(bm + r * 64 + cp);
            float lo, hi;
            unpk(mcc[j], lo, hi);
            if (vA) atomicAdd(macc + cp * 132 + pA, lo + bmv);
            if (vB) atomicAdd(macc + cp * 132 + pB, hi + bmv);
        }
        __syncwarp();
    }
    __syncthreads();

    // mean over 4 + relu
    for (int e = tid; e < 8192; e += 256) {
        int idx = (e >> 7) * 132 + (e & 127);
        macc[idx] = fmaxf(macc[idx] * 0.25f, 0.f);
    }
    // stage Wo into xs region (rows, stride 68)
    {
        const float4* wo4 = (const float4*)Wo;
        for (int e4 = tid; e4 < 1024; e4 += 256) {
            int o = e4 >> 4, c4 = (e4 & 15) << 2;
            *(float4*)(xs + o * 68 + c4) = wo4[e4];
        }
    }
    __syncthreads();

    // out projection: warp handles pixel octs o8 = w, w+8
    for (int o8 = w; o8 < 16; o8 += 8) {
        int pb = o8 * 8 + pp * 2;
        unsigned long long acc[8];
#pragma unroll
        for (int j = 0; j < 8; ++j) acc[j] = 0ull;
#pragma unroll 2
        for (int c4 = 0; c4 < 16; ++c4) {
            unsigned long long mv[4];
#pragma unroll
            for (int i = 0; i < 4; ++i)
                mv[i] = *(const unsigned long long*)(macc + (c4 * 4 + i) * 132 + pb);
#pragma unroll
            for (int j = 0; j < 8; ++j) {
                float4 wq = *(const float4*)(xs + (og + 8 * j) * 68 + c4 * 4);
                fma2(acc[j], mv[0], pk2(wq.x, wq.x));
                fma2(acc[j], mv[1], pk2(wq.y, wq.y));
                fma2(acc[j], mv[2], pk2(wq.z, wq.z));
                fma2(acc[j], mv[3], pk2(wq.w, wq.w));
            }
        }
        float* outb = out + bimg * 262144 + hwb + pb;
#pragma unroll
        for (int j = 0; j < 8; ++j) {
            int co = og + 8 * j;
            float bov = __ldg(bo + co);
            float lo, hi;
            unpk(acc[j], lo, hi);
            float2 o2 = make_float2(fmaxf(lo + bov, 0.f), fmaxf(hi + bov, 0.f));
            *(float2*)(outb + co * 4096) = o2;
        }
    }
}

// ============================================================
extern "C" void kernel_launch(void* const* d_in, const int* in_sizes, int n_in,
                              void* d_out, int out_size) {
    const float* x    = (const float*)d_in[0];
    const float* rims = (const float*)d_in[1];
    const float* Wk   = (const float*)d_in[2];
    const float* bk   = (const float*)d_in[3];
    const float* Wv   = (const float*)d_in[4];
    const float* bv   = (const float*)d_in[5];
    const float* Wq   = (const float*)d_in[6];
    const float* bq   = (const float*)d_in[7];
    const float* Wm   = (const float*)d_in[8];
    const float* bm   = (const float*)d_in[9];
    const float* Wo   = (const float*)d_in[10];
    const float* bo   = (const float*)d_in[11];
    float* out = (float*)d_out;

    cudaFuncSetAttribute(kB, cudaFuncAttributeMaxDynamicSharedMemorySize, SMEM_B);
    cudaFuncSetAttribute(kC, cudaFuncAttributeMaxDynamicSharedMemorySize, SMEM_C);

    kA<<<1, 1024>>>(rims, Wq, bq, bk);
    kB<<<512, 256, SMEM_B>>>(x, Wk, bk);
    kC<<<256, 256, SMEM_C>>>(x, Wv, bv, Wm, bm, Wo, bo, out);
}

// round 4
// speedup vs baseline: 1.9229x; 1.1663x over previous
#include <cuda_runtime.h>
#include <cuda_bf16.h>
#include <math.h>

// B=8, C=64, H=64, W=64, R=16, HD=4, D=16, K=4, OC=1024
// NPX=32768; x[B,C,H,W]: ch stride 4096, img stride 262144.
#define NPX 32768

__device__ float    g_cn[64];
__device__ unsigned g_sel[NPX];
// compaction outputs
__device__ int      g_npad;        // nact rounded up to 128
__device__ int      g_nreal;       // actual active count
__device__ int      g_src[1152];   // original channel per compacted slot
__device__ int      g_grp[1152];   // group id (r*4+hd) per compacted slot (64 = dummy)
__device__ float    g_bkq[1152];   // bk*qk per compacted slot
__device__ float    g_scl[1152];   // qk per compacted slot
__device__ float    g_Wkc[64 * 1024];  // transposed compacted scaled Wk: [c][slot]

__device__ __forceinline__ unsigned long long pk2(float lo, float hi) {
    unsigned long long r;
    asm("mov.b64 %0, {%1, %2};" : "=l"(r) : "f"(lo), "f"(hi));
    return r;
}
__device__ __forceinline__ void fma2(unsigned long long& d, unsigned long long a,
                                     unsigned long long b) {
    asm("fma.rn.f32x2 %0, %1, %2, %0;" : "+l"(d) : "l"(a), "l"(b));
}
__device__ __forceinline__ void unpk(unsigned long long v, float& lo, float& hi) {
    asm("mov.b64 {%0, %1}, %2;" : "=f"(lo), "=f"(hi) : "l"(v));
}

// ============================================================
// Kernel A1: qk + null constants + compaction scan. 1 block x 1024.
// ============================================================
__global__ void kA1(const float* __restrict__ rims, const float* __restrict__ Wq,
                    const float* __restrict__ bq, const float* __restrict__ bk) {
    __shared__ float qs[1024];
    __shared__ int sc[1024];
    int o = threadIdx.x;
    int r = o >> 6;
    const float4* rrow = (const float4*)(rims + r * 64);
    const float4* wrow = (const float4*)(Wq + o * 64);
    float s = bq[o];
#pragma unroll
    for (int c4 = 0; c4 < 16; ++c4) {
        float4 w = wrow[c4];
        float4 rv = rrow[c4];
        s = fmaf(rv.x, w.x, s);
        s = fmaf(rv.y, w.y, s);
        s = fmaf(rv.z, w.z, s);
        s = fmaf(rv.w, w.w, s);
    }
    float qk = fmaxf(s, 0.f);
    float bko = bk[o];
    qs[o] = qk * fmaxf(bko, 0.f);
    int active = (qk > 0.f) ? 1 : 0;
    sc[o] = active;
    __syncthreads();
    if (o < 64) {                  // null constants
        float cn = 0.f;
#pragma unroll
        for (int d = 0; d < 16; ++d) cn += qs[o * 16 + d];
        g_cn[o] = cn;
    }
    // inclusive scan over sc
    for (int off = 1; off < 1024; off <<= 1) {
        int v = 0;
        if (o >= off) v = sc[o - off];
        __syncthreads();
        sc[o] += v;
        __syncthreads();
    }
    if (active) {
        int p = sc[o] - 1;
        g_src[p] = o;
        g_grp[p] = o >> 4;
        g_bkq[p] = bko * qk;
        g_scl[p] = qk;
    }
    int nact = sc[1023];
    int npad = (nact + 127) & ~127;
    if (o == 0) { g_npad = npad; g_nreal = nact; }
    if (o < npad - nact) {
        int p = nact + o;
        g_src[p] = 0;
        g_grp[p] = 64;     // dummy group
        g_bkq[p] = 0.f;
        g_scl[p] = 0.f;
    }
}

// ============================================================
// Kernel A2: build transposed scaled compacted weights g_Wkc[c][slot].
// 8 blocks x 256: block b covers slots [b*128, b*128+128), thread half-c range.
// ============================================================
__global__ void kA2(const float* __restrict__ Wk) {
    int row = blockIdx.x * 128 + (threadIdx.x & 127);
    int ch  = (threadIdx.x >> 7) * 32;
    int npad = g_npad;
    if (row >= npad) return;
    float scl = g_scl[row];
    int src = g_src[row];
    const float4* wr = (const float4*)(Wk + src * 64 + ch);
#pragma unroll
    for (int c4 = 0; c4 < 8; ++c4) {
        float4 w = __ldg(wr + c4);
        int c = ch + c4 * 4;
        g_Wkc[(c + 0) * 1024 + row] = w.x * scl;
        g_Wkc[(c + 1) * 1024 + row] = w.y * scl;
        g_Wkc[(c + 2) * 1024 + row] = w.z * scl;
        g_Wkc[(c + 3) * 1024 + row] = w.w * scl;
    }
}

// ============================================================
// Kernel B: compacted keyf GEMM + scores + top-4. Block = 64 px, 256 threads.
// Dynamic chunks of 128 compacted outs; thread tile = 8 outs x 4 px.
// Out-pair f32x2: weights are adjacent pairs from transposed smem, x duplicated.
// smem: xs[64][64] + ws[64][132] + ip[65][68]
// ============================================================
#define KB_WS   4096
#define KB_IP   (4096 + 64 * 132)
#define SMEM_B  ((4096 + 64 * 132 + 65 * 68) * 4)

__global__ void __launch_bounds__(256, 2) kB(const float* __restrict__ x) {
    extern __shared__ float sm[];
    float* xs = sm;            // [c][p] 64x64
    float* ws = sm + KB_WS;    // [c][o_l] 64x132
    float* ip = sm + KB_IP;    // [g][p] 65x68

    const int tid  = threadIdx.x;
    const int pi0  = blockIdx.x * 64;
    const int bimg = pi0 >> 12;
    const int hw   = pi0 & 4095;
    const float* xbase = x + bimg * 262144 + hw;

    for (int e4 = tid; e4 < 1024; e4 += 256) {
        int c = e4 >> 4, p = (e4 & 15) << 2;
        *(float4*)(xs + c * 64 + p) = *(const float4*)(xbase + c * 4096 + p);
    }
    for (int e = tid; e < 65 * 68; e += 256) ip[e] = 0.f;

    const int tx = tid & 15;   // px group of 4
    const int ty = tid >> 4;   // out octet 0..15
    const int npad = g_npad;

    for (int o0 = 0; o0 < npad; o0 += 128) {
        __syncthreads();
        // stage transposed chunk: ws[c][o_l] <- g_Wkc[c][o0+o_l], coalesced
        for (int e4 = tid; e4 < 2048; e4 += 256) {
            int c = e4 >> 5, o4 = (e4 & 31) << 2;
            *(float4*)(ws + c * 132 + o4) = *(const float4*)(g_Wkc + c * 1024 + o0 + o4);
        }
        __syncthreads();

        unsigned long long acc[16];   // [opair 0..3][px 0..3]
#pragma unroll
        for (int i = 0; i < 16; ++i) acc[i] = 0ull;
        const float* wbase = ws + ty * 8;
        const float* xrow  = xs + tx * 4;

#pragma unroll 8
        for (int k = 0; k < 64; ++k) {
            float4 xv = *(const float4*)(xrow + k * 64);
            unsigned long long xd0 = pk2(xv.x, xv.x);
            unsigned long long xd1 = pk2(xv.y, xv.y);
            unsigned long long xd2 = pk2(xv.z, xv.z);
            unsigned long long xd3 = pk2(xv.w, xv.w);
            ulonglong2 wa = *(const ulonglong2*)(wbase + k * 132);
            ulonglong2 wb = *(const ulonglong2*)(wbase + k * 132 + 4);
            fma2(acc[0],  wa.x, xd0); fma2(acc[1],  wa.x, xd1);
            fma2(acc[2],  wa.x, xd2); fma2(acc[3],  wa.x, xd3);
            fma2(acc[4],  wa.y, xd0); fma2(acc[5],  wa.y, xd1);
            fma2(acc[6],  wa.y, xd2); fma2(acc[7],  wa.y, xd3);
            fma2(acc[8],  wb.x, xd0); fma2(acc[9],  wb.x, xd1);
            fma2(acc[10], wb.x, xd2); fma2(acc[11], wb.x, xd3);
            fma2(acc[12], wb.y, xd0); fma2(acc[13], wb.y, xd1);
            fma2(acc[14], wb.y, xd2); fma2(acc[15], wb.y, xd3);
        }

        // epilogue: term = relu(acc + bkq), run-flush by group into ip
        const int ob = o0 + ty * 8;
        int   grp[8];
        float bkq[8];
#pragma unroll
        for (int j = 0; j < 8; ++j) {
            grp[j] = __ldg(g_grp + ob + j);
            bkq[j] = __ldg(g_bkq + ob + j);
        }
#pragma unroll
        for (int px = 0; px < 4; ++px) {
            float s = 0.f;
            int gp = grp[0];
#pragma unroll
            for (int op = 0; op < 4; ++op) {
                float lo, hi;
                unpk(acc[op * 4 + px], lo, hi);
                int j0 = 2 * op;
                if (grp[j0] != gp) { atomicAdd(ip + gp * 68 + tx * 4 + px, s); s = 0.f; gp = grp[j0]; }
                s += fmaxf(lo + bkq[j0], 0.f);
                if (grp[j0 + 1] != gp) { atomicAdd(ip + gp * 68 + tx * 4 + px, s); s = 0.f; gp = grp[j0 + 1]; }
                s += fmaxf(hi + bkq[j0 + 1], 0.f);
            }
            atomicAdd(ip + gp * 68 + tx * 4 + px, s);
        }
    }
    __syncthreads();

    if (tid < 64) {
        int p = tid;
        float sc[16];
#pragma unroll
        for (int r = 0; r < 16; ++r) {
            float s = 0.f;
#pragma unroll
            for (int hd = 0; hd < 4; ++hd) {
                float v = ip[(r * 4 + hd) * 68 + p] - g_cn[r * 4 + hd];
                s += 1.f / (1.f + expf(-v));
            }
            sc[r] = s;
        }
        unsigned sel = 0;
#pragma unroll
        for (int kk = 0; kk < 4; ++kk) {
            int best = 0;
            float bvv = sc[0];
#pragma unroll
            for (int r = 1; r < 16; ++r)
                if (sc[r] > bvv) { bvv = sc[r]; best = r; }
            sel |= (unsigned)best << (8 * kk);
            sc[best] = -1e30f;
        }
        g_sel[pi0 + p] = sel;
    }
}

// ============================================================
// Kernel C: selective val+merge (f32x2), mean, relu, out projection.
// (unchanged from round 2)
// ============================================================
#define CC_XS     0
#define CC_MACC   8192
#define CC_VAL    (8192 + 64 * 132)
#define CC_MISC   (CC_VAL + 8 * 64 * 8)
#define SMEM_C    ((CC_MISC + 16 + 512 + 96 + 1) * 4)

__global__ void __launch_bounds__(256, 2) kC(const float* __restrict__ x,
                                             const float* __restrict__ Wv,
                                             const float* __restrict__ bv,
                                             const float* __restrict__ Wm,
                                             const float* __restrict__ bm,
                                             const float* __restrict__ Wo,
                                             const float* __restrict__ bo,
                                             float* __restrict__ out) {
    extern __shared__ float sm[];
    float* xs   = sm + CC_XS;     // [c][p] 64x128   (later reused as wo[64][68])
    float* macc = sm + CC_MACC;   // [c'][px] 64x132
    float* vbuf = sm + CC_VAL;    // [warp][d][slot] 8x64x8
    int* rimcnt = (int*)(sm + CC_MISC);
    unsigned char* rimlist = (unsigned char*)(rimcnt + 16);   // [16][128]
    int* tasks  = (int*)(rimlist + 2048);                      // [96]
    int* ntaskp = tasks + 96;

    const int tid  = threadIdx.x;
    const int w    = tid >> 5;
    const int lane = tid & 31;
    const int og   = lane >> 2;
    const int pp   = lane & 3;

    const int pi0  = blockIdx.x * 128;
    const int bimg = pi0 >> 12;
    const int hwb  = pi0 & 4095;
    const float* xbase = x + bimg * 262144 + hwb;

    for (int e4 = tid; e4 < 2048; e4 += 256) {
        int c = e4 >> 5, p = (e4 & 31) << 2;
        *(float4*)(xs + c * 128 + p) = *(const float4*)(xbase + c * 4096 + p);
    }
    for (int e = tid; e < 8448; e += 256) macc[e] = 0.f;
    if (tid < 16) rimcnt[tid] = 0;
    __syncthreads();

    if (tid < 128) {
        unsigned sel = g_sel[pi0 + tid];
#pragma unroll
        for (int j = 0; j < 4; ++j) {
            int r = (sel >> (8 * j)) & 15;
            int slot = atomicAdd(&rimcnt[r], 1);
            rimlist[r * 128 + slot] = (unsigned char)tid;
        }
    }
    __syncthreads();
    if (tid == 0) {
        int n = 0;
        for (int r = 0; r < 16; ++r) {
            int c = rimcnt[r];
            for (int s = 0; s < c; s += 8) tasks[n++] = (r << 8) | s;
        }
        *ntaskp = n;
    }
    __syncthreads();

    const int ntask = *ntaskp;
    const int nper  = (ntask + 7) >> 3;
    const int t0 = w * nper;
    const int t1 = min(t0 + nper, ntask);
    float* vb = vbuf + w * 512;

    for (int ti = t0; ti < t1; ++ti) {
        int tk = tasks[ti];
        int r = tk >> 8, s = tk & 255;
        int cnt = rimcnt[r] - s;
        if (cnt > 8) cnt = 8;
        const unsigned char* pl = rimlist + r * 128 + s;
        int i0 = pp * 2, i1 = i0 + 1;
        bool vA = i0 < cnt, vB = i1 < cnt;
        int pA = pl[vA ? i0 : 0];
        int pB = pl[vB ? i1 : 0];

        unsigned long long acc[8];
#pragma unroll
        for (int j = 0; j < 8; ++j) acc[j] = 0ull;
        const float4* wvr = (const float4*)(Wv + r * 4096);
#pragma unroll 2
        for (int c4 = 0; c4 < 16; ++c4) {
            unsigned long long xv[4];
#pragma unroll
            for (int i = 0; i < 4; ++i) {
                const float* xr = xs + (c4 * 4 + i) * 128;
                xv[i] = pk2(xr[pA], xr[pB]);
            }
#pragma unroll
            for (int j = 0; j < 8; ++j) {
                float4 wq = __ldg(&wvr[(og + 8 * j) * 16 + c4]);
                fma2(acc[j], xv[0], pk2(wq.x, wq.x));
                fma2(acc[j], xv[1], pk2(wq.y, wq.y));
                fma2(acc[j], xv[2], pk2(wq.z, wq.z));
                fma2(acc[j], xv[3], pk2(wq.w, wq.w));
            }
        }
#pragma unroll
        for (int j = 0; j < 8; ++j) {
            int d = og + 8 * j;
            float bvv = __ldg(bv + r * 64 + d);
            float lo, hi;
            unpk(acc[j], lo, hi);
            float2 o2 = make_float2(fmaxf(lo + bvv, 0.f), fmaxf(hi + bvv, 0.f));
            *(float2*)(vb + d * 8 + pp * 2) = o2;
        }
        __syncwarp();

        unsigned long long mcc[8];
#pragma unroll
        for (int j = 0; j < 8; ++j) mcc[j] = 0ull;
        const float4* wmr = (const float4*)(Wm + r * 4096);
#pragma unroll 2
        for (int d4 = 0; d4 < 16; ++d4) {
            unsigned long long vv[4];
#pragma unroll
            for (int i = 0; i < 4; ++i)
                vv[i] = *(const unsigned long long*)(vb + (d4 * 4 + i) * 8 + pp * 2);
#pragma unroll
            for (int j = 0; j < 8; ++j) {
                float4 wq = __ldg(&wmr[(og + 8 * j) * 16 + d4]);
                fma2(mcc[j], vv[0], pk2(wq.x, wq.x));
                fma2(mcc[j], vv[1], pk2(wq.y, wq.y));
                fma2(mcc[j], vv[2], pk2(wq.z, wq.z));
                fma2(mcc[j], vv[3], pk2(wq.w, wq.w));
            }
        }
#pragma unroll
        for (int j = 0; j < 8; ++j) {
            int cp = og + 8 * j;
            float bmv = __ldg(bm + r * 64 + cp);
            float lo, hi;
            unpk(mcc[j], lo, hi);
            if (vA) atomicAdd(macc + cp * 132 + pA, lo + bmv);
            if (vB) atomicAdd(macc + cp * 132 + pB, hi + bmv);
        }
        __syncwarp();
    }
    __syncthreads();

    for (int e = tid; e < 8192; e += 256) {
        int idx = (e >> 7) * 132 + (e & 127);
        macc[idx] = fmaxf(macc[idx] * 0.25f, 0.f);
    }
    {
        const float4* wo4 = (const float4*)Wo;
        for (int e4 = tid; e4 < 1024; e4 += 256) {
            int o = e4 >> 4, c4 = (e4 & 15) << 2;
            *(float4*)(xs + o * 68 + c4) = wo4[e4];
        }
    }
    __syncthreads();

    for (int o8 = w; o8 < 16; o8 += 8) {
        int pb = o8 * 8 + pp * 2;
        unsigned long long acc[8];
#pragma unroll
        for (int j = 0; j < 8; ++j) acc[j] = 0ull;
#pragma unroll 2
        for (int c4 = 0; c4 < 16; ++c4) {
            unsigned long long mv[4];
#pragma unroll
            for (int i = 0; i < 4; ++i)
                mv[i] = *(const unsigned long long*)(macc + (c4 * 4 + i) * 132 + pb);
#pragma unroll
            for (int j = 0; j < 8; ++j) {
                float4 wq = *(const float4*)(xs + (og + 8 * j) * 68 + c4 * 4);
                fma2(acc[j], mv[0], pk2(wq.x, wq.x));
                fma2(acc[j], mv[1], pk2(wq.y, wq.y));
                fma2(acc[j], mv[2], pk2(wq.z, wq.z));
                fma2(acc[j], mv[3], pk2(wq.w, wq.w));
            }
        }
        float* outb = out + bimg * 262144 + hwb + pb;
#pragma unroll
        for (int j = 0; j < 8; ++j) {
            int co = og + 8 * j;
            float bov = __ldg(bo + co);
            float lo, hi;
            unpk(acc[j], lo, hi);
            float2 o2 = make_float2(fmaxf(lo + bov, 0.f), fmaxf(hi + bov, 0.f));
            *(float2*)(outb + co * 4096) = o2;
        }
    }
}

// ============================================================
extern "C" void kernel_launch(void* const* d_in, const int* in_sizes, int n_in,
                              void* d_out, int out_size) {
    const float* x    = (const float*)d_in[0];
    const float* rims = (const float*)d_in[1];
    const float* Wk   = (const float*)d_in[2];
    const float* bk   = (const float*)d_in[3];
    const float* Wv   = (const float*)d_in[4];
    const float* bv   = (const float*)d_in[5];
    const float* Wq   = (const float*)d_in[6];
    const float* bq   = (const float*)d_in[7];
    const float* Wm   = (const float*)d_in[8];
    const float* bm   = (const float*)d_in[9];
    const float* Wo   = (const float*)d_in[10];
    const float* bo   = (const float*)d_in[11];
    float* out = (float*)d_out;

    cudaFuncSetAttribute(kB, cudaFuncAttributeMaxDynamicSharedMemorySize, SMEM_B);
    cudaFuncSetAttribute(kC, cudaFuncAttributeMaxDynamicSharedMemorySize, SMEM_C);

    kA1<<<1, 1024>>>(rims, Wq, bq, bk);
    kA2<<<8, 256>>>(Wk);
    kB<<<512, 256, SMEM_B>>>(x);
    kC<<<256, 256, SMEM_C>>>(x, Wv, bv, Wm, bm, Wo, bo, out);
}

// round 8
// speedup vs baseline: 2.0100x; 1.0453x over previous
#include <cuda_runtime.h>
#include <cuda_bf16.h>
#include <math.h>

// B=8, C=64, H=64, W=64, R=16, HD=4, D=16, K=4, OC=1024
// NPX=32768; x[B,C,H,W]: ch stride 4096, img stride 262144.
#define NPX 32768

__device__ float    g_cn[64];
__device__ unsigned g_sel[NPX];
__device__ float    g_qkA[1024];
// compaction outputs (kB path)
__device__ int      g_npad;
__device__ int      g_nreal;
__device__ int      g_src[1152];
__device__ int      g_grp[1152];
__device__ float    g_bkq[1152];
__device__ float    g_scl[1152];
__device__ float    g_Wkc[64 * 1024];
// transposed weights for kC
__device__ float    g_WvT[16 * 4096];   // [rim][c][colperm(o)]
__device__ float    g_WmT[16 * 4096];   // [rim][c][colperm(o)]
__device__ float    g_WoT[4096];        // [c][o]

__device__ __forceinline__ unsigned long long pk2(float lo, float hi) {
    unsigned long long r;
    asm("mov.b64 %0, {%1, %2};" : "=l"(r) : "f"(lo), "f"(hi));
    return r;
}
__device__ __forceinline__ void fma2(unsigned long long& d, unsigned long long a,
                                     unsigned long long b) {
    asm("fma.rn.f32x2 %0, %1, %2, %0;" : "+l"(d) : "l"(a), "l"(b));
}
__device__ __forceinline__ void unpk(unsigned long long v, float& lo, float& hi) {
    asm("mov.b64 {%0, %1}, %2;" : "=f"(lo), "=f"(hi) : "l"(v));
}

// ============================================================
// Kernel A1a: qk per output channel. 8 blocks x 128.
// ============================================================
__global__ void kA1a(const float* __restrict__ rims, const float* __restrict__ Wq,
                     const float* __restrict__ bq) {
    int o = blockIdx.x * 128 + threadIdx.x;
    int r = o >> 6;
    const float4* rrow = (const float4*)(rims + r * 64);
    const float4* wrow = (const float4*)(Wq + o * 64);
    float s = bq[o];
#pragma unroll
    for (int c4 = 0; c4 < 16; ++c4) {
        float4 w = wrow[c4];
        float4 rv = rrow[c4];
        s = fmaf(rv.x, w.x, s);
        s = fmaf(rv.y, w.y, s);
        s = fmaf(rv.z, w.z, s);
        s = fmaf(rv.w, w.w, s);
    }
    g_qkA[o] = fmaxf(s, 0.f);
}

// ============================================================
// Kernel A1b: null constants + compaction scan. 1 block x 1024.
// ============================================================
__global__ void kA1b(const float* __restrict__ bk) {
    __shared__ float qs[1024];
    __shared__ int sc[1024];
    int o = threadIdx.x;
    float qk = g_qkA[o];
    float bko = bk[o];
    qs[o] = qk * fmaxf(bko, 0.f);
    int active = (qk > 0.f) ? 1 : 0;
    sc[o] = active;
    __syncthreads();
    if (o < 64) {
        float cn = 0.f;
#pragma unroll
        for (int d = 0; d < 16; ++d) cn += qs[o * 16 + d];
        g_cn[o] = cn;
    }
    for (int off = 1; off < 1024; off <<= 1) {
        int v = 0;
        if (o >= off) v = sc[o - off];
        __syncthreads();
        sc[o] += v;
        __syncthreads();
    }
    if (active) {
        int p = sc[o] - 1;
        g_src[p] = o;
        g_grp[p] = o >> 4;
        g_bkq[p] = bko * qk;
        g_scl[p] = qk;
    }
    int nact = sc[1023];
    int npad = (nact + 127) & ~127;
    if (o == 0) { g_npad = npad; g_nreal = nact; }
    if (o < npad - nact) {
        int p = nact + o;
        g_src[p] = 0;
        g_grp[p] = 64;
        g_bkq[p] = 0.f;
        g_scl[p] = 0.f;
    }
}

// ============================================================
// Kernel A2: transposed scaled compacted Wk -> g_Wkc[c][slot]. 8 x 256.
// ============================================================
__global__ void kA2(const float* __restrict__ Wk) {
    int row = blockIdx.x * 128 + (threadIdx.x & 127);
    int ch  = (threadIdx.x >> 7) * 32;
    int npad = g_npad;
    if (row >= npad) return;
    float scl = g_scl[row];
    int src = g_src[row];
    const float4* wr = (const float4*)(Wk + src * 64 + ch);
#pragma unroll
    for (int c4 = 0; c4 < 8; ++c4) {
        float4 w = __ldg(wr + c4);
        int c = ch + c4 * 4;
        g_Wkc[(c + 0) * 1024 + row] = w.x * scl;
        g_Wkc[(c + 1) * 1024 + row] = w.y * scl;
        g_Wkc[(c + 2) * 1024 + row] = w.z * scl;
        g_Wkc[(c + 3) * 1024 + row] = w.w * scl;
    }
}

// ============================================================
// Kernel W: one-time weight transposes for kC. 33 blocks x 256.
// Wv/Wm: [rim][o][c] -> [rim][c][colperm(o)], colperm(o) = (o&15)*4 + (o>>4).
// Wo: [o][c] -> [c][o].
// ============================================================
__global__ void kW(const float* __restrict__ Wv, const float* __restrict__ Wm,
                   const float* __restrict__ Wo) {
    int mat = blockIdx.x;
    const float* src;
    float* dst;
    bool perm = true;
    if (mat < 16)      { src = Wv + mat * 4096;       dst = g_WvT + mat * 4096; }
    else if (mat < 32) { src = Wm + (mat - 16) * 4096; dst = g_WmT + (mat - 16) * 4096; }
    else               { src = Wo;                     dst = g_WoT; perm = false; }
    for (int e = threadIdx.x; e < 1024; e += 256) {
        int o = e >> 4, c4 = e & 15;
        float4 v = __ldg((const float4*)src + e);
        int col = perm ? ((o & 15) * 4 + (o >> 4)) : o;
        int c = c4 * 4;
        dst[(c + 0) * 64 + col] = v.x;
        dst[(c + 1) * 64 + col] = v.y;
        dst[(c + 2) * 64 + col] = v.z;
        dst[(c + 3) * 64 + col] = v.w;
    }
}

// ============================================================
// Kernel B: compacted keyf GEMM + scores + top-4.
// ============================================================
#define KB_WS   4096
#define KB_IP   (4096 + 64 * 132)
#define SMEM_B  ((4096 + 64 * 132 + 65 * 68) * 4)

__global__ void __launch_bounds__(256, 2) kB(const float* __restrict__ x) {
    extern __shared__ float sm[];
    float* xs = sm;
    float* ws = sm + KB_WS;
    float* ip = sm + KB_IP;

    const int tid  = threadIdx.x;
    const int pi0  = blockIdx.x * 64;
    const int bimg = pi0 >> 12;
    const int hw   = pi0 & 4095;
    const float* xbase = x + bimg * 262144 + hw;

    for (int e4 = tid; e4 < 1024; e4 += 256) {
        int c = e4 >> 4, p = (e4 & 15) << 2;
        *(float4*)(xs + c * 64 + p) = *(const float4*)(xbase + c * 4096 + p);
    }
    for (int e = tid; e < 65 * 68; e += 256) ip[e] = 0.f;

    const int tx = tid & 15;
    const int ty = tid >> 4;
    const int npad = g_npad;

    for (int o0 = 0; o0 < npad; o0 += 128) {
        __syncthreads();
        for (int e4 = tid; e4 < 2048; e4 += 256) {
            int c = e4 >> 5, o4 = (e4 & 31) << 2;
            *(float4*)(ws + c * 132 + o4) = *(const float4*)(g_Wkc + c * 1024 + o0 + o4);
        }
        __syncthreads();

        unsigned long long acc[16];
#pragma unroll
        for (int i = 0; i < 16; ++i) acc[i] = 0ull;
        const float* wbase = ws + ty * 8;
        const float* xrow  = xs + tx * 4;

#pragma unroll 8
        for (int k = 0; k < 64; ++k) {
            float4 xv = *(const float4*)(xrow + k * 64);
            unsigned long long xd0 = pk2(xv.x, xv.x);
            unsigned long long xd1 = pk2(xv.y, xv.y);
            unsigned long long xd2 = pk2(xv.z, xv.z);
            unsigned long long xd3 = pk2(xv.w, xv.w);
            ulonglong2 wa = *(const ulonglong2*)(wbase + k * 132);
            ulonglong2 wb = *(const ulonglong2*)(wbase + k * 132 + 4);
            fma2(acc[0],  wa.x, xd0); fma2(acc[1],  wa.x, xd1);
            fma2(acc[2],  wa.x, xd2); fma2(acc[3],  wa.x, xd3);
            fma2(acc[4],  wa.y, xd0); fma2(acc[5],  wa.y, xd1);
            fma2(acc[6],  wa.y, xd2); fma2(acc[7],  wa.y, xd3);
            fma2(acc[8],  wb.x, xd0); fma2(acc[9],  wb.x, xd1);
            fma2(acc[10], wb.x, xd2); fma2(acc[11], wb.x, xd3);
            fma2(acc[12], wb.y, xd0); fma2(acc[13], wb.y, xd1);
            fma2(acc[14], wb.y, xd2); fma2(acc[15], wb.y, xd3);
        }

        const int ob = o0 + ty * 8;
        int   grp[8];
        float bkq[8];
#pragma unroll
        for (int j = 0; j < 8; ++j) {
            grp[j] = __ldg(g_grp + ob + j);
            bkq[j] = __ldg(g_bkq + ob + j);
        }
#pragma unroll
        for (int px = 0; px < 4; ++px) {
            float s = 0.f;
            int gp = grp[0];
#pragma unroll
            for (int op = 0; op < 4; ++op) {
                float lo, hi;
                unpk(acc[op * 4 + px], lo, hi);
                int j0 = 2 * op;
                if (grp[j0] != gp) { atomicAdd(ip + gp * 68 + tx * 4 + px, s); s = 0.f; gp = grp[j0]; }
                s += fmaxf(lo + bkq[j0], 0.f);
                if (grp[j0 + 1] != gp) { atomicAdd(ip + gp * 68 + tx * 4 + px, s); s = 0.f; gp = grp[j0 + 1]; }
                s += fmaxf(hi + bkq[j0 + 1], 0.f);
            }
            atomicAdd(ip + gp * 68 + tx * 4 + px, s);
        }
    }
    __syncthreads();

    if (tid < 64) {
        int p = tid;
        float sc[16];
#pragma unroll
        for (int r = 0; r < 16; ++r) {
            float s = 0.f;
#pragma unroll
            for (int hd = 0; hd < 4; ++hd) {
                float v = ip[(r * 4 + hd) * 68 + p] - g_cn[r * 4 + hd];
                s += 1.f / (1.f + expf(-v));
            }
            sc[r] = s;
        }
        unsigned sel = 0;
#pragma unroll
        for (int kk = 0; kk < 4; ++kk) {
            int best = 0;
            float bvv = sc[0];
#pragma unroll
            for (int r = 1; r < 16; ++r)
                if (sc[r] > bvv) { bvv = sc[r]; best = r; }
            sel |= (unsigned)best << (8 * kk);
            sc[best] = -1e30f;
        }
        g_sel[pi0 + p] = sel;
    }
}

// ============================================================
// Kernel C: block = 128 px, 256 threads, 256 blocks.
// Rim batches of 2; weights staged in smem; slot-gathered f32x2 GEMMs.
// Tile oq (0..15) owns outs {oq,oq+16,oq+32,oq+48} (ws cols permuted adjacent).
// ============================================================
#define GS 148                      // xg/vb slot stride (floats)
#define CO_XS   0                   // xs[64][132]
#define CO_MACC 8448                // macc[64][132]
#define CO_XG   16896               // xg[64][148]
#define CO_VB   26368               // vb[64][148]
#define CO_WS   35840               // ws[64][280]: Wv at m*68+col, Wm at 140+m*68+col
#define CO_MISC 53760
// misc: rimcnt[16], pn[16], rimlist u8[16*128]=512w, slot2px u8[148]->40w
#define SMEM_C  ((53760 + 16 + 16 + 512 + 40) * 4)

__global__ void __launch_bounds__(256) kC(const float* __restrict__ x,
                                          const float* __restrict__ bv,
                                          const float* __restrict__ bm,
                                          const float* __restrict__ bo,
                                          float* __restrict__ out) {
    extern __shared__ float sm[];
    float* xs   = sm + CO_XS;
    float* macc = sm + CO_MACC;
    float* xg   = sm + CO_XG;
    float* vb   = sm + CO_VB;
    float* ws   = sm + CO_WS;
    int* rimcnt = (int*)(sm + CO_MISC);
    int* pn     = rimcnt + 16;
    unsigned char* rimlist = (unsigned char*)(pn + 16);       // [16][128]
    unsigned char* slot2px = rimlist + 2048;                   // [148]

    const int tid  = threadIdx.x;
    const int pi0  = blockIdx.x * 128;
    const int bimg = pi0 >> 12;
    const int hwb  = pi0 & 4095;
    const float* xbase = x + bimg * 262144 + hwb;

    for (int e4 = tid; e4 < 2048; e4 += 256) {
        int c = e4 >> 5, p = (e4 & 31) << 2;
        *(float4*)(xs + c * 132 + p) = *(const float4*)(xbase + c * 4096 + p);
    }
    for (int e = tid; e < 256; e += 256) {
        int c = e >> 2;
        xs[c * 132 + 128 + (e & 3)] = 0.f;
    }
    for (int e = tid; e < 8448; e += 256) macc[e] = 0.f;
    if (tid < 16) rimcnt[tid] = 0;
    __syncthreads();

    if (tid < 128) {
        unsigned sel = g_sel[pi0 + tid];
#pragma unroll
        for (int j = 0; j < 4; ++j) {
            int r = (sel >> (8 * j)) & 15;
            int slot = atomicAdd(&rimcnt[r], 1);
            rimlist[r * 128 + slot] = (unsigned char)tid;
        }
    }
    __syncthreads();
    if (tid < 16) pn[tid] = (rimcnt[tid] + 3) & ~3;
    __syncthreads();

    for (int b = 0; b < 8; ++b) {
        const int r0 = 2 * b;
        const int pn0 = pn[r0];
        const int nsl = pn0 + pn[r0 + 1];

        for (int e = tid; e < 4096; e += 256) {
            int mat = e >> 11;
            int rest = e & 2047;
            int m = rest >> 10, c = (rest >> 4) & 63, o4 = rest & 15;
            const float* srcb = (mat ? g_WmT : g_WvT) + (r0 + m) * 4096 + c * 64 + o4 * 4;
            float4 v = *(const float4*)srcb;
            *(float4*)(ws + c * 280 + mat * 140 + m * 68 + o4 * 4) = v;
        }

        for (int w0 = 0; w0 < nsl; w0 += GS) {
            int wn = nsl - w0;
            if (wn > GS) wn = GS;
            __syncthreads();
            if (tid < wn) {
                int s = w0 + tid;
                int m = (s >= pn0) ? 1 : 0;
                int rim = r0 + m;
                int i = s - (m ? pn0 : 0);
                slot2px[tid] = (i < rimcnt[rim]) ? rimlist[rim * 128 + i] : 128;
            }
            __syncthreads();
            for (int c = tid >> 5; c < 64; c += 8)
                for (int sl = tid & 31; sl < wn; sl += 32)
                    xg[c * GS + sl] = xs[c * 132 + slot2px[sl]];
            __syncthreads();

            // ---- val GEMM ----
            int ntile = (wn >> 2) << 4;
            for (int t = tid; t < ntile; t += 256) {
                int sq = t >> 4, oq = t & 15;
                int s0 = sq * 4;
                int m = ((w0 + s0) >= pn0) ? 1 : 0;
                int rim = r0 + m;
                const float* wcol = ws + m * 68 + oq * 4;
                unsigned long long acc[8];
#pragma unroll
                for (int i = 0; i < 8; ++i) acc[i] = 0ull;
#pragma unroll 4
                for (int c = 0; c < 64; ++c) {
                    float4 xv = *(const float4*)(xg + c * GS + s0);
                    ulonglong2 wp = *(const ulonglong2*)(wcol + c * 280);
                    unsigned long long x0 = pk2(xv.x, xv.x);
                    unsigned long long x1 = pk2(xv.y, xv.y);
                    unsigned long long x2 = pk2(xv.z, xv.z);
                    unsigned long long x3 = pk2(xv.w, xv.w);
                    fma2(acc[0], wp.x, x0); fma2(acc[1], wp.x, x1);
                    fma2(acc[2], wp.x, x2); fma2(acc[3], wp.x, x3);
                    fma2(acc[4], wp.y, x0); fma2(acc[5], wp.y, x1);
                    fma2(acc[6], wp.y, x2); fma2(acc[7], wp.y, x3);
                }
                float b0 = __ldg(bv + rim * 64 + oq);
                float b1 = __ldg(bv + rim * 64 + oq + 16);
                float b2 = __ldg(bv + rim * 64 + oq + 32);
                float b3 = __ldg(bv + rim * 64 + oq + 48);
#pragma unroll
                for (int sl = 0; sl < 4; ++sl) {
                    float lo, hi;
                    unpk(acc[sl], lo, hi);
                    vb[(oq)      * GS + s0 + sl] = fmaxf(lo + b0, 0.f);
                    vb[(oq + 16) * GS + s0 + sl] = fmaxf(hi + b1, 0.f);
                    unpk(acc[4 + sl], lo, hi);
                    vb[(oq + 32) * GS + s0 + sl] = fmaxf(lo + b2, 0.f);
                    vb[(oq + 48) * GS + s0 + sl] = fmaxf(hi + b3, 0.f);
                }
            }
            __syncthreads();

            // ---- merge GEMM ----
            for (int t = tid; t < ntile; t += 256) {
                int sq = t >> 4, oq = t & 15;
                int s0 = sq * 4;
                int m = ((w0 + s0) >= pn0) ? 1 : 0;
                int rim = r0 + m;
                const float* wcol = ws + 140 + m * 68 + oq * 4;
                unsigned long long acc[8];
#pragma unroll
                for (int i = 0; i < 8; ++i) acc[i] = 0ull;
#pragma unroll 4
                for (int d = 0; d < 64; ++d) {
                    float4 xv = *(const float4*)(vb + d * GS + s0);
                    ulonglong2 wp = *(const ulonglong2*)(wcol + d * 280);
                    unsigned long long x0 = pk2(xv.x, xv.x);
                    unsigned long long x1 = pk2(xv.y, xv.y);
                    unsigned long long x2 = pk2(xv.z, xv.z);
                    unsigned long long x3 = pk2(xv.w, xv.w);
                    fma2(acc[0], wp.x, x0); fma2(acc[1], wp.x, x1);
                    fma2(acc[2], wp.x, x2); fma2(acc[3], wp.x, x3);
                    fma2(acc[4], wp.y, x0); fma2(acc[5], wp.y, x1);
                    fma2(acc[6], wp.y, x2); fma2(acc[7], wp.y, x3);
                }
                float b0 = __ldg(bm + rim * 64 + oq);
                float b1 = __ldg(bm + rim * 64 + oq + 16);
                float b2 = __ldg(bm + rim * 64 + oq + 32);
                float b3 = __ldg(bm + rim * 64 + oq + 48);
#pragma unroll
                for (int sl = 0; sl < 4; ++sl) {
                    int px = slot2px[s0 + sl];
                    float lo, hi;
                    unpk(acc[sl], lo, hi);
                    atomicAdd(macc + (oq)      * 132 + px, lo + b0);
                    atomicAdd(macc + (oq + 16) * 132 + px, hi + b1);
                    unpk(acc[4 + sl], lo, hi);
                    atomicAdd(macc + (oq + 32) * 132 + px, lo + b2);
                    atomicAdd(macc + (oq + 48) * 132 + px, hi + b3);
                }
            }
        }
        __syncthreads();
    }

    for (int e = tid; e < 8448; e += 256) macc[e] = fmaxf(macc[e] * 0.25f, 0.f);
    for (int e4 = tid; e4 < 1024; e4 += 256) {
        int c = e4 >> 4, o4 = (e4 & 15) << 2;
        float4 v = *(const float4*)(g_WoT + c * 64 + o4);
        *(float4*)(ws + c * 280 + o4) = v;
    }
    __syncthreads();

    for (int t = tid; t < 512; t += 256) {
        int pq = t & 63;
        int oc = t >> 6;
        unsigned long long acc[8];
#pragma unroll
        for (int j = 0; j < 8; ++j) acc[j] = 0ull;
#pragma unroll 4
        for (int c = 0; c < 64; ++c) {
            unsigned long long mv = *(const unsigned long long*)(macc + c * 132 + pq * 2);
            float4 wA = *(const float4*)(ws + c * 280 + oc * 8);
            float4 wB = *(const float4*)(ws + c * 280 + oc * 8 + 4);
            fma2(acc[0], mv, pk2(wA.x, wA.x));
            fma2(acc[1], mv, pk2(wA.y, wA.y));
            fma2(acc[2], mv, pk2(wA.z, wA.z));
            fma2(acc[3], mv, pk2(wA.w, wA.w));
            fma2(acc[4], mv, pk2(wB.x, wB.x));
            fma2(acc[5], mv, pk2(wB.y, wB.y));
            fma2(acc[6], mv, pk2(wB.z, wB.z));
            fma2(acc[7], mv, pk2(wB.w, wB.w));
        }
        float* outb = out + bimg * 262144 + hwb + pq * 2;
#pragma unroll
        for (int j = 0; j < 8; ++j) {
            int co = oc * 8 + j;
            float bov = __ldg(bo + co);
            float lo, hi;
            unpk(acc[j], lo, hi);
            float2 o2 = make_float2(fmaxf(lo + bov, 0.f), fmaxf(hi + bov, 0.f));
            *(float2*)(outb + co * 4096) = o2;
        }
    }
}

// ============================================================
extern "C" void kernel_launch(void* const* d_in, const int* in_sizes, int n_in,
                              void* d_out, int out_size) {
    const float* x    = (const float*)d_in[0];
    const float* rims = (const float*)d_in[1];
    const float* Wk   = (const float*)d_in[2];
    const float* bk   = (const float*)d_in[3];
    const float* Wv   = (const float*)d_in[4];
    const float* bv   = (const float*)d_in[5];
    const float* Wq   = (const float*)d_in[6];
    const float* bq   = (const float*)d_in[7];
    const float* Wm   = (const float*)d_in[8];
    const float* bm   = (const float*)d_in[9];
    const float* Wo   = (const float*)d_in[10];
    const float* bo   = (const float*)d_in[11];
    float* out = (float*)d_out;

    cudaFuncSetAttribute(kB, cudaFuncAttributeMaxDynamicSharedMemorySize, SMEM_B);
    cudaFuncSetAttribute(kC, cudaFuncAttributeMaxDynamicSharedMemorySize, SMEM_C);

    kA1a<<<8, 128>>>(rims, Wq, bq);
    kW<<<33, 256>>>(Wv, Wm, Wo);
    kA1b<<<1, 1024>>>(bk);
    kA2<<<8, 256>>>(Wk);
    kB<<<512, 256, SMEM_B>>>(x);
    kC<<<256, 256, SMEM_C>>>(x, bv, bm, bo, out);
}